// round 15
// baseline (speedup 1.0000x reference)
#include <cuda_runtime.h>
#include <math.h>
#include <float.h>
#include <stdint.h>

#define Bb 2
#define Ss 2048
#define Nn 1024
#define Hh 1024
#define NHh 16
#define Dd 64

// Scratch (__device__ globals: allocation-free rule)
__device__ float g_q[Bb * Ss * Hh];     // tf32-rounded, pre-scaled by 0.125
__device__ float g_k[Bb * Nn * Hh];     // tf32-rounded
__device__ float g_v[Bb * Nn * Hh];     // tf32-rounded
__device__ float g_ao[Bb * Ss * Hh];    // tf32-rounded attention out
__device__ float g_tq[Bb * Ss * Hh];
__device__ float g_kvr[Bb * Nn * Hh];
__device__ float g_wq[Hh * Hh];
__device__ float g_wk[Hh * Hh];
__device__ float g_wv[Hh * Hh];
__device__ float g_wo[Hh * Hh];
__device__ float g_vmean[Bb * Hh];
__device__ float g_vpart[16][Bb * Hh];

__device__ __forceinline__ float f2tf32(float x) {
    uint32_t u;
    asm("cvt.rna.tf32.f32 %0, %1;" : "=r"(u) : "f"(x));
    return __uint_as_float(u);
}

__device__ __forceinline__ void cp16(void* smem, const void* g) {
    uint32_t s = (uint32_t)__cvta_generic_to_shared(smem);
    asm volatile("cp.async.cg.shared.global [%0], [%1], 16;" :: "r"(s), "l"(g));
}

// ---------------------------------------------------------------------------
__global__ void round_tf32_kernel(const float* __restrict__ x, float* __restrict__ y, int n)
{
    int i = (blockIdx.x * blockDim.x + threadIdx.x) * 4;
    if (i >= n) return;
    float4 v = *(const float4*)(x + i);
    float4 r;
    r.x = f2tf32(v.x); r.y = f2tf32(v.y); r.z = f2tf32(v.z); r.w = f2tf32(v.w);
    *(float4*)(y + i) = r;
}

// ---------------------------------------------------------------------------
// Y[m,n] = scale * sum_k X[m,k] * W[n,k], K=N=1024. Inputs pre-rounded tf32.
// 128x128 CTA tile, K-tile 32, 256 threads, 3-stage cp.async, 1 barrier/tile.
// gridDim.z==2 selects (Wa,Ya)/(Wb,Yb). roundOut: round result to tf32.
// ---------------------------------------------------------------------------
__global__ __launch_bounds__(256) void gemm_tf32(
    const float* __restrict__ X,
    const float* __restrict__ Wa, float* __restrict__ Ya,
    const float* __restrict__ Wb, float* __restrict__ Yb,
    float scale, int roundOut)
{
    const float* W = (blockIdx.z == 0) ? Wa : Wb;
    float* Y = (blockIdx.z == 0) ? Ya : Yb;
    const int K = 1024;
    const int S = 3;
    __shared__ float As[3][128][36];
    __shared__ float Bs[3][128][36];

    int tid = threadIdx.x;
    int wid = tid >> 5;
    int lane = tid & 31;
    int m0 = blockIdx.y * 128;
    int n0 = blockIdx.x * 128;
    int warp_m = (wid >> 1) * 32;
    int warp_n = (wid & 1) * 64;
    int lr = tid >> 3;
    int lc = (tid & 7) * 4;
    const int gr = lane >> 2;
    const int gc = lane & 3;

    float acc[2][8][4];
#pragma unroll
    for (int mi = 0; mi < 2; mi++)
#pragma unroll
        for (int ni = 0; ni < 8; ni++)
#pragma unroll
            for (int r = 0; r < 4; r++) acc[mi][ni][r] = 0.f;

    // prologue: stages 0..S-2
#pragma unroll
    for (int s = 0; s < S - 1; s++) {
        int k0 = s * 32;
#pragma unroll
        for (int rr = 0; rr < 4; rr++) {
            int r = lr + rr * 32;
            cp16(&As[s][r][lc], X + (size_t)(m0 + r) * K + k0 + lc);
            cp16(&Bs[s][r][lc], W + (size_t)(n0 + r) * K + k0 + lc);
        }
        asm volatile("cp.async.commit_group;" ::: "memory");
    }

    for (int kt = 0; kt < 32; kt++) {
        int cur = kt % S;
        asm volatile("cp.async.wait_group %0;" :: "n"(S - 2) : "memory");
        __syncthreads();

        // issue load for tile kt+S-1 (writes the stage consumed at kt-1)
        if (kt + S - 1 < 32) {
            int nxt = (kt + S - 1) % S;
            int k0 = (kt + S - 1) * 32;
#pragma unroll
            for (int rr = 0; rr < 4; rr++) {
                int r = lr + rr * 32;
                cp16(&As[nxt][r][lc], X + (size_t)(m0 + r) * K + k0 + lc);
                cp16(&Bs[nxt][r][lc], W + (size_t)(n0 + r) * K + k0 + lc);
            }
            asm volatile("cp.async.commit_group;" ::: "memory");
        } else {
            asm volatile("cp.async.commit_group;" ::: "memory");   // keep group count uniform
        }

#pragma unroll
        for (int ks = 0; ks < 4; ks++) {
            int kb = ks * 8;
            uint32_t a[2][4];
#pragma unroll
            for (int mi = 0; mi < 2; mi++) {
                int r = warp_m + mi * 16 + gr;
                int c = kb + gc;
                a[mi][0] = __float_as_uint(As[cur][r][c]);
                a[mi][1] = __float_as_uint(As[cur][r + 8][c]);
                a[mi][2] = __float_as_uint(As[cur][r][c + 4]);
                a[mi][3] = __float_as_uint(As[cur][r + 8][c + 4]);
            }
            uint32_t b[8][2];
#pragma unroll
            for (int ni = 0; ni < 8; ni++) {
                int n = warp_n + ni * 8 + gr;
                int c = kb + gc;
                b[ni][0] = __float_as_uint(Bs[cur][n][c]);
                b[ni][1] = __float_as_uint(Bs[cur][n][c + 4]);
            }
#pragma unroll
            for (int mi = 0; mi < 2; mi++)
#pragma unroll
                for (int ni = 0; ni < 8; ni++) {
                    asm volatile(
                        "mma.sync.aligned.m16n8k8.row.col.f32.tf32.tf32.f32 "
                        "{%0,%1,%2,%3}, {%4,%5,%6,%7}, {%8,%9}, {%0,%1,%2,%3};\n"
                        : "+f"(acc[mi][ni][0]), "+f"(acc[mi][ni][1]),
                          "+f"(acc[mi][ni][2]), "+f"(acc[mi][ni][3])
                        : "r"(a[mi][0]), "r"(a[mi][1]), "r"(a[mi][2]), "r"(a[mi][3]),
                          "r"(b[ni][0]), "r"(b[ni][1]));
                }
        }
    }

#pragma unroll
    for (int mi = 0; mi < 2; mi++) {
#pragma unroll
        for (int ni = 0; ni < 8; ni++) {
            int row = m0 + warp_m + mi * 16 + gr;
            int col = n0 + warp_n + ni * 8 + gc * 2;
            float o0 = acc[mi][ni][0] * scale, o1 = acc[mi][ni][1] * scale;
            float o2 = acc[mi][ni][2] * scale, o3 = acc[mi][ni][3] * scale;
            if (roundOut) {
                o0 = f2tf32(o0); o1 = f2tf32(o1); o2 = f2tf32(o2); o3 = f2tf32(o3);
            }
            *(float2*)&Y[(size_t)row * 1024 + col] = make_float2(o0, o1);
            *(float2*)&Y[(size_t)(row + 8) * 1024 + col] = make_float2(o2, o3);
        }
    }
}

// ---------------------------------------------------------------------------
__global__ void vmean_part_kernel(const float* __restrict__ V, float* __restrict__ vp)
{
    int idx = blockIdx.x * blockDim.x + threadIdx.x;
    int chunk = blockIdx.y;
    if (idx >= Bb * Hh) return;
    int b = idx >> 10;
    int hd = idx & 1023;
    const float* p = V + (size_t)b * Nn * Hh + hd + (size_t)chunk * (Nn / 16) * Hh;
    float s = 0.f;
#pragma unroll 4
    for (int n = 0; n < Nn / 16; n++) s += p[(size_t)n * Hh];
    vp[chunk * (Bb * Hh) + idx] = s;
}

__global__ void vmean_reduce_kernel(const float* __restrict__ vp, float* __restrict__ vm)
{
    int idx = blockIdx.x * blockDim.x + threadIdx.x;
    if (idx >= Bb * Hh) return;
    float s = 0.f;
#pragma unroll
    for (int c = 0; c < 16; c++) s += vp[c * (Bb * Hh) + idx];
    vm[idx] = s * (1.0f / Nn);
}

// ---------------------------------------------------------------------------
// Flash attention (tf32 mma). Q pre-scaled+rounded, K/V pre-rounded.
// cp.async double-buffered KV tiles; upfront binary search over sorted
// block_ends gives the exact visible tile count (no wasted tile loads).
// 128 threads (4 warps), 64 queries/CTA, warp = 16 query rows.
// ---------------------------------------------------------------------------
__global__ __launch_bounds__(128) void flash_tf32_kernel(
    const float* __restrict__ Q, const float* __restrict__ Kp,
    const float* __restrict__ Vp, const int* __restrict__ be,
    const float* __restrict__ vmean, float* __restrict__ O)
{
    __shared__ float Qs[64][68];
    __shared__ float Ks[2][64][68];
    __shared__ float Vs[2][64][68];
    __shared__ float Ps[64][68];
    __shared__ int   bes[2][64];

    int tid = threadIdx.x;
    int wid = tid >> 5;
    int lane = tid & 31;
    const int gr = lane >> 2;
    const int gc = lane & 3;
    int b = blockIdx.z, h = blockIdx.y, t0 = blockIdx.x * 64;
    const int tmax = t0 + 63;

    const float* Qg = Q + ((size_t)b * Ss + t0) * Hh + h * Dd;
    const float* Kg = Kp + (size_t)b * Nn * Hh + h * Dd;
    const float* Vg = Vp + (size_t)b * Nn * Hh + h * Dd;

    // n_vis = #ends <= tmax (be sorted ascending); uniform binary search
    int lo = 0, hi = Nn;
    while (lo < hi) {
        int mid = (lo + hi) >> 1;
        if (be[mid] <= tmax) lo = mid + 1; else hi = mid;
    }
    const int n_tiles = (lo + 63) >> 6;

    const int rbase = wid * 16 + gr;
    float m_i[2] = {-FLT_MAX, -FLT_MAX};
    float l_i[2] = {0.f, 0.f};
    float acc[8][4];
#pragma unroll
    for (int ni = 0; ni < 8; ni++)
#pragma unroll
        for (int r = 0; r < 4; r++) acc[ni][r] = 0.f;

    // Q tile prologue load (cp.async)
#pragma unroll
    for (int p = 0; p < 8; p++) {
        int f = p * 128 + tid;
        int r = f >> 4, c = (f & 15) * 4;
        cp16(&Qs[r][c], Qg + (size_t)r * Hh + c);
    }

    if (n_tiles > 0) {
        // prefetch KV tile 0
#pragma unroll
        for (int p = 0; p < 8; p++) {
            int f = p * 128 + tid;
            int r = f >> 4, c = (f & 15) * 4;
            cp16(&Ks[0][r][c], Kg + (size_t)r * Hh + c);
            cp16(&Vs[0][r][c], Vg + (size_t)r * Hh + c);
        }
        if (tid < 64) bes[0][tid] = be[tid];
        asm volatile("cp.async.commit_group;" ::: "memory");

        for (int it = 0; it < n_tiles; it++) {
            int cur = it & 1;
            asm volatile("cp.async.wait_group 0;" ::: "memory");
            __syncthreads();

            if (it + 1 < n_tiles) {
                int nxt = cur ^ 1;
                int n0 = (it + 1) * 64;
#pragma unroll
                for (int p = 0; p < 8; p++) {
                    int f = p * 128 + tid;
                    int r = f >> 4, c = (f & 15) * 4;
                    cp16(&Ks[nxt][r][c], Kg + (size_t)(n0 + r) * Hh + c);
                    cp16(&Vs[nxt][r][c], Vg + (size_t)(n0 + r) * Hh + c);
                }
                if (tid < 64) bes[nxt][tid] = be[n0 + tid];
            }
            asm volatile("cp.async.commit_group;" ::: "memory");

            // S = Q K^T
            float s[8][4];
#pragma unroll
            for (int ni = 0; ni < 8; ni++)
#pragma unroll
                for (int r = 0; r < 4; r++) s[ni][r] = 0.f;
#pragma unroll
            for (int kb = 0; kb < 8; kb++) {
                int c = kb * 8;
                uint32_t a0 = __float_as_uint(Qs[rbase][c + gc]);
                uint32_t a1 = __float_as_uint(Qs[rbase + 8][c + gc]);
                uint32_t a2 = __float_as_uint(Qs[rbase][c + gc + 4]);
                uint32_t a3 = __float_as_uint(Qs[rbase + 8][c + gc + 4]);
#pragma unroll
                for (int ni = 0; ni < 8; ni++) {
                    uint32_t b0 = __float_as_uint(Ks[cur][ni * 8 + gr][c + gc]);
                    uint32_t b1 = __float_as_uint(Ks[cur][ni * 8 + gr][c + gc + 4]);
                    asm volatile(
                        "mma.sync.aligned.m16n8k8.row.col.f32.tf32.tf32.f32 "
                        "{%0,%1,%2,%3}, {%4,%5,%6,%7}, {%8,%9}, {%0,%1,%2,%3};\n"
                        : "+f"(s[ni][0]), "+f"(s[ni][1]), "+f"(s[ni][2]), "+f"(s[ni][3])
                        : "r"(a0), "r"(a1), "r"(a2), "r"(a3), "r"(b0), "r"(b1));
                }
            }

            int bcol[8][2];
#pragma unroll
            for (int ni = 0; ni < 8; ni++) {
                bcol[ni][0] = bes[cur][ni * 8 + gc * 2];
                bcol[ni][1] = bes[cur][ni * 8 + gc * 2 + 1];
            }

#pragma unroll
            for (int half = 0; half < 2; half++) {
                int t = t0 + rbase + half * 8;
                float sv[8][2];
                float rm = -FLT_MAX;
#pragma unroll
                for (int ni = 0; ni < 8; ni++) {
                    sv[ni][0] = (bcol[ni][0] <= t) ? s[ni][half * 2 + 0] : -FLT_MAX;
                    sv[ni][1] = (bcol[ni][1] <= t) ? s[ni][half * 2 + 1] : -FLT_MAX;
                    rm = fmaxf(rm, fmaxf(sv[ni][0], sv[ni][1]));
                }
                rm = fmaxf(rm, __shfl_xor_sync(0xffffffffu, rm, 1));
                rm = fmaxf(rm, __shfl_xor_sync(0xffffffffu, rm, 2));
                float nm = fmaxf(m_i[half], rm);
                float rl = 0.f;
                float pv[8][2];
#pragma unroll
                for (int ni = 0; ni < 8; ni++) {
                    pv[ni][0] = (sv[ni][0] == -FLT_MAX) ? 0.f : __expf(sv[ni][0] - nm);
                    pv[ni][1] = (sv[ni][1] == -FLT_MAX) ? 0.f : __expf(sv[ni][1] - nm);
                    rl += pv[ni][0] + pv[ni][1];
                }
                rl += __shfl_xor_sync(0xffffffffu, rl, 1);
                rl += __shfl_xor_sync(0xffffffffu, rl, 2);
                float alpha = (m_i[half] == nm) ? 1.f : __expf(m_i[half] - nm);
                m_i[half] = nm;
                l_i[half] = l_i[half] * alpha + rl;
                int row = rbase + half * 8;
#pragma unroll
                for (int ni = 0; ni < 8; ni++) {
                    acc[ni][half * 2 + 0] *= alpha;
                    acc[ni][half * 2 + 1] *= alpha;
                    Ps[row][ni * 8 + gc * 2]     = f2tf32(pv[ni][0]);
                    Ps[row][ni * 8 + gc * 2 + 1] = f2tf32(pv[ni][1]);
                }
            }
            __syncwarp();   // Ps rows are warp-private

            // acc += P @ V
#pragma unroll
            for (int kb = 0; kb < 8; kb++) {
                int c = kb * 8;
                uint32_t a0 = __float_as_uint(Ps[rbase][c + gc]);
                uint32_t a1 = __float_as_uint(Ps[rbase + 8][c + gc]);
                uint32_t a2 = __float_as_uint(Ps[rbase][c + gc + 4]);
                uint32_t a3 = __float_as_uint(Ps[rbase + 8][c + gc + 4]);
#pragma unroll
                for (int ni = 0; ni < 8; ni++) {
                    uint32_t b0 = __float_as_uint(Vs[cur][c + gc][ni * 8 + gr]);
                    uint32_t b1 = __float_as_uint(Vs[cur][c + gc + 4][ni * 8 + gr]);
                    asm volatile(
                        "mma.sync.aligned.m16n8k8.row.col.f32.tf32.tf32.f32 "
                        "{%0,%1,%2,%3}, {%4,%5,%6,%7}, {%8,%9}, {%0,%1,%2,%3};\n"
                        : "+f"(acc[ni][0]), "+f"(acc[ni][1]), "+f"(acc[ni][2]), "+f"(acc[ni][3])
                        : "r"(a0), "r"(a1), "r"(a2), "r"(a3), "r"(b0), "r"(b1));
                }
            }
        }
    }
    asm volatile("cp.async.wait_group 0;" ::: "memory");

    // epilogue (output rounded to tf32: feeds Wo GEMM)
    float* Og = O + ((size_t)b * Ss + t0) * Hh + h * Dd;
    const float* vmb = vmean + b * Hh + h * Dd;
#pragma unroll
    for (int half = 0; half < 2; half++) {
        int row = rbase + half * 8;
        bool uni = (l_i[half] == 0.f);
        float inv = uni ? 0.f : (1.f / l_i[half]);
#pragma unroll
        for (int ni = 0; ni < 8; ni++) {
            int col = ni * 8 + gc * 2;
            float o0 = uni ? vmb[col]     : acc[ni][half * 2 + 0] * inv;
            float o1 = uni ? vmb[col + 1] : acc[ni][half * 2 + 1] * inv;
            *(float2*)&Og[(size_t)row * Hh + col] = make_float2(f2tf32(o0), f2tf32(o1));
        }
    }
}

// ---------------------------------------------------------------------------
extern "C" void kernel_launch(void* const* d_in, const int* in_sizes, int n_in,
                              void* d_out, int out_size)
{
    const float* token_q  = (const float*)d_in[0];
    const float* block_kv = (const float*)d_in[1];
    const int*   blk_ends = (const int*)d_in[2];
    const float* Wq       = (const float*)d_in[3];
    const float* Wk       = (const float*)d_in[4];
    const float* Wv       = (const float*)d_in[5];
    const float* Wo       = (const float*)d_in[6];
    float* out = (float*)d_out;

    float *q, *k, *v, *ao, *vm, *vp, *tq, *kvr, *wq, *wk, *wv, *wo;
    cudaGetSymbolAddress((void**)&q,   g_q);
    cudaGetSymbolAddress((void**)&k,   g_k);
    cudaGetSymbolAddress((void**)&v,   g_v);
    cudaGetSymbolAddress((void**)&ao,  g_ao);
    cudaGetSymbolAddress((void**)&vm,  g_vmean);
    cudaGetSymbolAddress((void**)&vp,  g_vpart);
    cudaGetSymbolAddress((void**)&tq,  g_tq);
    cudaGetSymbolAddress((void**)&kvr, g_kvr);
    cudaGetSymbolAddress((void**)&wq,  g_wq);
    cudaGetSymbolAddress((void**)&wk,  g_wk);
    cudaGetSymbolAddress((void**)&wv,  g_wv);
    cudaGetSymbolAddress((void**)&wo,  g_wo);

    const int nTQ = Bb * Ss * Hh, nKV = Bb * Nn * Hh, nW = Hh * Hh;
    round_tf32_kernel<<<nTQ / 1024, 256>>>(token_q, tq, nTQ);
    round_tf32_kernel<<<nKV / 1024, 256>>>(block_kv, kvr, nKV);
    round_tf32_kernel<<<nW / 1024, 256>>>(Wq, wq, nW);
    round_tf32_kernel<<<nW / 1024, 256>>>(Wk, wk, nW);
    round_tf32_kernel<<<nW / 1024, 256>>>(Wv, wv, nW);
    round_tf32_kernel<<<nW / 1024, 256>>>(Wo, wo, nW);

    // Q proj: fold 1/sqrt(D)=0.125 and tf32-round; K/V proj: tf32-round
    gemm_tf32<<<dim3(8, (Bb * Ss) / 128, 1), 256>>>(tq, wq, q, wq, q, 0.125f, 1);
    gemm_tf32<<<dim3(8, (Bb * Nn) / 128, 2), 256>>>(kvr, wk, k, wv, v, 1.0f, 1);

    vmean_part_kernel<<<dim3((Bb * Hh + 255) / 256, 16), 256>>>(v, vp);
    vmean_reduce_kernel<<<(Bb * Hh + 255) / 256, 256>>>(vp, vm);

    flash_tf32_kernel<<<dim3(Ss / 64, NHh, Bb), 128>>>(q, k, v, blk_ends, vm, ao);

    // Output projection (fp32 out, no rounding)
    gemm_tf32<<<dim3(8, (Bb * Ss) / 128, 1), 256>>>(ao, wo, out, wo, out, 1.0f, 0);
}

// round 16
// speedup vs baseline: 1.0027x; 1.0027x over previous
#include <cuda_runtime.h>
#include <math.h>
#include <float.h>
#include <stdint.h>

#define Bb 2
#define Ss 2048
#define Nn 1024
#define Hh 1024
#define NHh 16
#define Dd 64

// Scratch (__device__ globals: allocation-free rule)
__device__ float g_q[Bb * Ss * Hh];     // tf32-rounded, pre-scaled by 0.125
__device__ float g_k[Bb * Nn * Hh];     // tf32-rounded
__device__ float g_v[Bb * Nn * Hh];     // tf32-rounded
__device__ float g_ao[Bb * Ss * Hh];    // tf32-rounded attention out
__device__ float g_tq[Bb * Ss * Hh];
__device__ float g_kvr[Bb * Nn * Hh];
__device__ float g_wq[Hh * Hh];
__device__ float g_wk[Hh * Hh];
__device__ float g_wv[Hh * Hh];
__device__ float g_wo[Hh * Hh];
__device__ float g_vmean[Bb * Hh];
__device__ float g_vpart[16][Bb * Hh];

__device__ __forceinline__ float f2tf32(float x) {
    uint32_t u;
    asm("cvt.rna.tf32.f32 %0, %1;" : "=r"(u) : "f"(x));
    return __uint_as_float(u);
}

__device__ __forceinline__ void cp16(void* smem, const void* g) {
    uint32_t s = (uint32_t)__cvta_generic_to_shared(smem);
    asm volatile("cp.async.cg.shared.global [%0], [%1], 16;" :: "r"(s), "l"(g));
}

// ---------------------------------------------------------------------------
__global__ void round_tf32_kernel(const float* __restrict__ x, float* __restrict__ y, int n)
{
    int i = (blockIdx.x * blockDim.x + threadIdx.x) * 4;
    if (i >= n) return;
    float4 v = *(const float4*)(x + i);
    float4 r;
    r.x = f2tf32(v.x); r.y = f2tf32(v.y); r.z = f2tf32(v.z); r.w = f2tf32(v.w);
    *(float4*)(y + i) = r;
}

// ---------------------------------------------------------------------------
// Y[m,n] = scale * sum_k X[m,k] * W[n,k], K=N=1024. Inputs pre-rounded tf32.
// 128x128 CTA tile, K-tile 32, 256 threads, 3-stage cp.async, 1 barrier/tile.
// gridDim.z==2 selects (Wa,Ya)/(Wb,Yb). roundOut: round result to tf32.
// ---------------------------------------------------------------------------
__global__ __launch_bounds__(256) void gemm_tf32(
    const float* __restrict__ X,
    const float* __restrict__ Wa, float* __restrict__ Ya,
    const float* __restrict__ Wb, float* __restrict__ Yb,
    float scale, int roundOut)
{
    const float* W = (blockIdx.z == 0) ? Wa : Wb;
    float* Y = (blockIdx.z == 0) ? Ya : Yb;
    const int K = 1024;
    const int S = 3;
    __shared__ float As[3][128][36];
    __shared__ float Bs[3][128][36];

    int tid = threadIdx.x;
    int wid = tid >> 5;
    int lane = tid & 31;
    int m0 = blockIdx.y * 128;
    int n0 = blockIdx.x * 128;
    int warp_m = (wid >> 1) * 32;
    int warp_n = (wid & 1) * 64;
    int lr = tid >> 3;
    int lc = (tid & 7) * 4;
    const int gr = lane >> 2;
    const int gc = lane & 3;

    float acc[2][8][4];
#pragma unroll
    for (int mi = 0; mi < 2; mi++)
#pragma unroll
        for (int ni = 0; ni < 8; ni++)
#pragma unroll
            for (int r = 0; r < 4; r++) acc[mi][ni][r] = 0.f;

    // prologue: stages 0..S-2
#pragma unroll
    for (int s = 0; s < S - 1; s++) {
        int k0 = s * 32;
#pragma unroll
        for (int rr = 0; rr < 4; rr++) {
            int r = lr + rr * 32;
            cp16(&As[s][r][lc], X + (size_t)(m0 + r) * K + k0 + lc);
            cp16(&Bs[s][r][lc], W + (size_t)(n0 + r) * K + k0 + lc);
        }
        asm volatile("cp.async.commit_group;" ::: "memory");
    }

    for (int kt = 0; kt < 32; kt++) {
        int cur = kt % S;
        asm volatile("cp.async.wait_group %0;" :: "n"(S - 2) : "memory");
        __syncthreads();

        // issue load for tile kt+S-1 (writes the stage consumed at kt-1)
        if (kt + S - 1 < 32) {
            int nxt = (kt + S - 1) % S;
            int k0 = (kt + S - 1) * 32;
#pragma unroll
            for (int rr = 0; rr < 4; rr++) {
                int r = lr + rr * 32;
                cp16(&As[nxt][r][lc], X + (size_t)(m0 + r) * K + k0 + lc);
                cp16(&Bs[nxt][r][lc], W + (size_t)(n0 + r) * K + k0 + lc);
            }
            asm volatile("cp.async.commit_group;" ::: "memory");
        } else {
            asm volatile("cp.async.commit_group;" ::: "memory");   // keep group count uniform
        }

#pragma unroll
        for (int ks = 0; ks < 4; ks++) {
            int kb = ks * 8;
            uint32_t a[2][4];
#pragma unroll
            for (int mi = 0; mi < 2; mi++) {
                int r = warp_m + mi * 16 + gr;
                int c = kb + gc;
                a[mi][0] = __float_as_uint(As[cur][r][c]);
                a[mi][1] = __float_as_uint(As[cur][r + 8][c]);
                a[mi][2] = __float_as_uint(As[cur][r][c + 4]);
                a[mi][3] = __float_as_uint(As[cur][r + 8][c + 4]);
            }
            uint32_t b[8][2];
#pragma unroll
            for (int ni = 0; ni < 8; ni++) {
                int n = warp_n + ni * 8 + gr;
                int c = kb + gc;
                b[ni][0] = __float_as_uint(Bs[cur][n][c]);
                b[ni][1] = __float_as_uint(Bs[cur][n][c + 4]);
            }
#pragma unroll
            for (int mi = 0; mi < 2; mi++)
#pragma unroll
                for (int ni = 0; ni < 8; ni++) {
                    asm volatile(
                        "mma.sync.aligned.m16n8k8.row.col.f32.tf32.tf32.f32 "
                        "{%0,%1,%2,%3}, {%4,%5,%6,%7}, {%8,%9}, {%0,%1,%2,%3};\n"
                        : "+f"(acc[mi][ni][0]), "+f"(acc[mi][ni][1]),
                          "+f"(acc[mi][ni][2]), "+f"(acc[mi][ni][3])
                        : "r"(a[mi][0]), "r"(a[mi][1]), "r"(a[mi][2]), "r"(a[mi][3]),
                          "r"(b[ni][0]), "r"(b[ni][1]));
                }
        }
    }

#pragma unroll
    for (int mi = 0; mi < 2; mi++) {
#pragma unroll
        for (int ni = 0; ni < 8; ni++) {
            int row = m0 + warp_m + mi * 16 + gr;
            int col = n0 + warp_n + ni * 8 + gc * 2;
            float o0 = acc[mi][ni][0] * scale, o1 = acc[mi][ni][1] * scale;
            float o2 = acc[mi][ni][2] * scale, o3 = acc[mi][ni][3] * scale;
            if (roundOut) {
                o0 = f2tf32(o0); o1 = f2tf32(o1); o2 = f2tf32(o2); o3 = f2tf32(o3);
            }
            *(float2*)&Y[(size_t)row * 1024 + col] = make_float2(o0, o1);
            *(float2*)&Y[(size_t)(row + 8) * 1024 + col] = make_float2(o2, o3);
        }
    }
}

// ---------------------------------------------------------------------------
__global__ void vmean_part_kernel(const float* __restrict__ V, float* __restrict__ vp)
{
    int idx = blockIdx.x * blockDim.x + threadIdx.x;
    int chunk = blockIdx.y;
    if (idx >= Bb * Hh) return;
    int b = idx >> 10;
    int hd = idx & 1023;
    const float* p = V + (size_t)b * Nn * Hh + hd + (size_t)chunk * (Nn / 16) * Hh;
    float s = 0.f;
#pragma unroll 4
    for (int n = 0; n < Nn / 16; n++) s += p[(size_t)n * Hh];
    vp[chunk * (Bb * Hh) + idx] = s;
}

__global__ void vmean_reduce_kernel(const float* __restrict__ vp, float* __restrict__ vm)
{
    int idx = blockIdx.x * blockDim.x + threadIdx.x;
    if (idx >= Bb * Hh) return;
    float s = 0.f;
#pragma unroll
    for (int c = 0; c < 16; c++) s += vp[c * (Bb * Hh) + idx];
    vm[idx] = s * (1.0f / Nn);
}

// ---------------------------------------------------------------------------
// Flash attention (tf32 mma). Q pre-scaled+rounded, K/V pre-rounded.
// cp.async double-buffered KV tiles; upfront binary search over sorted
// block_ends gives the exact visible tile count (no wasted tile loads).
// 128 threads (4 warps), 64 queries/CTA, warp = 16 query rows.
// ---------------------------------------------------------------------------
__global__ __launch_bounds__(128) void flash_tf32_kernel(
    const float* __restrict__ Q, const float* __restrict__ Kp,
    const float* __restrict__ Vp, const int* __restrict__ be,
    const float* __restrict__ vmean, float* __restrict__ O)
{
    __shared__ float Qs[64][68];
    __shared__ float Ks[2][64][68];
    __shared__ float Vs[2][64][68];
    __shared__ float Ps[64][68];
    __shared__ int   bes[2][64];

    int tid = threadIdx.x;
    int wid = tid >> 5;
    int lane = tid & 31;
    const int gr = lane >> 2;
    const int gc = lane & 3;
    int b = blockIdx.z, h = blockIdx.y, t0 = blockIdx.x * 64;
    const int tmax = t0 + 63;

    const float* Qg = Q + ((size_t)b * Ss + t0) * Hh + h * Dd;
    const float* Kg = Kp + (size_t)b * Nn * Hh + h * Dd;
    const float* Vg = Vp + (size_t)b * Nn * Hh + h * Dd;

    // n_vis = #ends <= tmax (be sorted ascending); uniform binary search
    int lo = 0, hi = Nn;
    while (lo < hi) {
        int mid = (lo + hi) >> 1;
        if (be[mid] <= tmax) lo = mid + 1; else hi = mid;
    }
    const int n_tiles = (lo + 63) >> 6;

    const int rbase = wid * 16 + gr;
    float m_i[2] = {-FLT_MAX, -FLT_MAX};
    float l_i[2] = {0.f, 0.f};
    float acc[8][4];
#pragma unroll
    for (int ni = 0; ni < 8; ni++)
#pragma unroll
        for (int r = 0; r < 4; r++) acc[ni][r] = 0.f;

    // Q tile prologue load (cp.async)
#pragma unroll
    for (int p = 0; p < 8; p++) {
        int f = p * 128 + tid;
        int r = f >> 4, c = (f & 15) * 4;
        cp16(&Qs[r][c], Qg + (size_t)r * Hh + c);
    }

    if (n_tiles > 0) {
        // prefetch KV tile 0
#pragma unroll
        for (int p = 0; p < 8; p++) {
            int f = p * 128 + tid;
            int r = f >> 4, c = (f & 15) * 4;
            cp16(&Ks[0][r][c], Kg + (size_t)r * Hh + c);
            cp16(&Vs[0][r][c], Vg + (size_t)r * Hh + c);
        }
        if (tid < 64) bes[0][tid] = be[tid];
        asm volatile("cp.async.commit_group;" ::: "memory");

        for (int it = 0; it < n_tiles; it++) {
            int cur = it & 1;
            asm volatile("cp.async.wait_group 0;" ::: "memory");
            __syncthreads();

            if (it + 1 < n_tiles) {
                int nxt = cur ^ 1;
                int n0 = (it + 1) * 64;
#pragma unroll
                for (int p = 0; p < 8; p++) {
                    int f = p * 128 + tid;
                    int r = f >> 4, c = (f & 15) * 4;
                    cp16(&Ks[nxt][r][c], Kg + (size_t)(n0 + r) * Hh + c);
                    cp16(&Vs[nxt][r][c], Vg + (size_t)(n0 + r) * Hh + c);
                }
                if (tid < 64) bes[nxt][tid] = be[n0 + tid];
            }
            asm volatile("cp.async.commit_group;" ::: "memory");

            // S = Q K^T
            float s[8][4];
#pragma unroll
            for (int ni = 0; ni < 8; ni++)
#pragma unroll
                for (int r = 0; r < 4; r++) s[ni][r] = 0.f;
#pragma unroll
            for (int kb = 0; kb < 8; kb++) {
                int c = kb * 8;
                uint32_t a0 = __float_as_uint(Qs[rbase][c + gc]);
                uint32_t a1 = __float_as_uint(Qs[rbase + 8][c + gc]);
                uint32_t a2 = __float_as_uint(Qs[rbase][c + gc + 4]);
                uint32_t a3 = __float_as_uint(Qs[rbase + 8][c + gc + 4]);
#pragma unroll
                for (int ni = 0; ni < 8; ni++) {
                    uint32_t b0 = __float_as_uint(Ks[cur][ni * 8 + gr][c + gc]);
                    uint32_t b1 = __float_as_uint(Ks[cur][ni * 8 + gr][c + gc + 4]);
                    asm volatile(
                        "mma.sync.aligned.m16n8k8.row.col.f32.tf32.tf32.f32 "
                        "{%0,%1,%2,%3}, {%4,%5,%6,%7}, {%8,%9}, {%0,%1,%2,%3};\n"
                        : "+f"(s[ni][0]), "+f"(s[ni][1]), "+f"(s[ni][2]), "+f"(s[ni][3])
                        : "r"(a0), "r"(a1), "r"(a2), "r"(a3), "r"(b0), "r"(b1));
                }
            }

            int bcol[8][2];
#pragma unroll
            for (int ni = 0; ni < 8; ni++) {
                bcol[ni][0] = bes[cur][ni * 8 + gc * 2];
                bcol[ni][1] = bes[cur][ni * 8 + gc * 2 + 1];
            }

#pragma unroll
            for (int half = 0; half < 2; half++) {
                int t = t0 + rbase + half * 8;
                float sv[8][2];
                float rm = -FLT_MAX;
#pragma unroll
                for (int ni = 0; ni < 8; ni++) {
                    sv[ni][0] = (bcol[ni][0] <= t) ? s[ni][half * 2 + 0] : -FLT_MAX;
                    sv[ni][1] = (bcol[ni][1] <= t) ? s[ni][half * 2 + 1] : -FLT_MAX;
                    rm = fmaxf(rm, fmaxf(sv[ni][0], sv[ni][1]));
                }
                rm = fmaxf(rm, __shfl_xor_sync(0xffffffffu, rm, 1));
                rm = fmaxf(rm, __shfl_xor_sync(0xffffffffu, rm, 2));
                float nm = fmaxf(m_i[half], rm);
                float rl = 0.f;
                float pv[8][2];
#pragma unroll
                for (int ni = 0; ni < 8; ni++) {
                    pv[ni][0] = (sv[ni][0] == -FLT_MAX) ? 0.f : __expf(sv[ni][0] - nm);
                    pv[ni][1] = (sv[ni][1] == -FLT_MAX) ? 0.f : __expf(sv[ni][1] - nm);
                    rl += pv[ni][0] + pv[ni][1];
                }
                rl += __shfl_xor_sync(0xffffffffu, rl, 1);
                rl += __shfl_xor_sync(0xffffffffu, rl, 2);
                float alpha = (m_i[half] == nm) ? 1.f : __expf(m_i[half] - nm);
                m_i[half] = nm;
                l_i[half] = l_i[half] * alpha + rl;
                int row = rbase + half * 8;
#pragma unroll
                for (int ni = 0; ni < 8; ni++) {
                    acc[ni][half * 2 + 0] *= alpha;
                    acc[ni][half * 2 + 1] *= alpha;
                    Ps[row][ni * 8 + gc * 2]     = f2tf32(pv[ni][0]);
                    Ps[row][ni * 8 + gc * 2 + 1] = f2tf32(pv[ni][1]);
                }
            }
            __syncwarp();   // Ps rows are warp-private

            // acc += P @ V
#pragma unroll
            for (int kb = 0; kb < 8; kb++) {
                int c = kb * 8;
                uint32_t a0 = __float_as_uint(Ps[rbase][c + gc]);
                uint32_t a1 = __float_as_uint(Ps[rbase + 8][c + gc]);
                uint32_t a2 = __float_as_uint(Ps[rbase][c + gc + 4]);
                uint32_t a3 = __float_as_uint(Ps[rbase + 8][c + gc + 4]);
#pragma unroll
                for (int ni = 0; ni < 8; ni++) {
                    uint32_t b0 = __float_as_uint(Vs[cur][c + gc][ni * 8 + gr]);
                    uint32_t b1 = __float_as_uint(Vs[cur][c + gc + 4][ni * 8 + gr]);
                    asm volatile(
                        "mma.sync.aligned.m16n8k8.row.col.f32.tf32.tf32.f32 "
                        "{%0,%1,%2,%3}, {%4,%5,%6,%7}, {%8,%9}, {%0,%1,%2,%3};\n"
                        : "+f"(acc[ni][0]), "+f"(acc[ni][1]), "+f"(acc[ni][2]), "+f"(acc[ni][3])
                        : "r"(a0), "r"(a1), "r"(a2), "r"(a3), "r"(b0), "r"(b1));
                }
            }
        }
    }
    asm volatile("cp.async.wait_group 0;" ::: "memory");

    // epilogue (output rounded to tf32: feeds Wo GEMM)
    float* Og = O + ((size_t)b * Ss + t0) * Hh + h * Dd;
    const float* vmb = vmean + b * Hh + h * Dd;
#pragma unroll
    for (int half = 0; half < 2; half++) {
        int row = rbase + half * 8;
        bool uni = (l_i[half] == 0.f);
        float inv = uni ? 0.f : (1.f / l_i[half]);
#pragma unroll
        for (int ni = 0; ni < 8; ni++) {
            int col = ni * 8 + gc * 2;
            float o0 = uni ? vmb[col]     : acc[ni][half * 2 + 0] * inv;
            float o1 = uni ? vmb[col + 1] : acc[ni][half * 2 + 1] * inv;
            *(float2*)&Og[(size_t)row * Hh + col] = make_float2(f2tf32(o0), f2tf32(o1));
        }
    }
}

// ---------------------------------------------------------------------------
extern "C" void kernel_launch(void* const* d_in, const int* in_sizes, int n_in,
                              void* d_out, int out_size)
{
    const float* token_q  = (const float*)d_in[0];
    const float* block_kv = (const float*)d_in[1];
    const int*   blk_ends = (const int*)d_in[2];
    const float* Wq       = (const float*)d_in[3];
    const float* Wk       = (const float*)d_in[4];
    const float* Wv       = (const float*)d_in[5];
    const float* Wo       = (const float*)d_in[6];
    float* out = (float*)d_out;

    float *q, *k, *v, *ao, *vm, *vp, *tq, *kvr, *wq, *wk, *wv, *wo;
    cudaGetSymbolAddress((void**)&q,   g_q);
    cudaGetSymbolAddress((void**)&k,   g_k);
    cudaGetSymbolAddress((void**)&v,   g_v);
    cudaGetSymbolAddress((void**)&ao,  g_ao);
    cudaGetSymbolAddress((void**)&vm,  g_vmean);
    cudaGetSymbolAddress((void**)&vp,  g_vpart);
    cudaGetSymbolAddress((void**)&tq,  g_tq);
    cudaGetSymbolAddress((void**)&kvr, g_kvr);
    cudaGetSymbolAddress((void**)&wq,  g_wq);
    cudaGetSymbolAddress((void**)&wk,  g_wk);
    cudaGetSymbolAddress((void**)&wv,  g_wv);
    cudaGetSymbolAddress((void**)&wo,  g_wo);

    const int nTQ = Bb * Ss * Hh, nKV = Bb * Nn * Hh, nW = Hh * Hh;
    round_tf32_kernel<<<nTQ / 1024, 256>>>(token_q, tq, nTQ);
    round_tf32_kernel<<<nKV / 1024, 256>>>(block_kv, kvr, nKV);
    round_tf32_kernel<<<nW / 1024, 256>>>(Wq, wq, nW);
    round_tf32_kernel<<<nW / 1024, 256>>>(Wk, wk, nW);
    round_tf32_kernel<<<nW / 1024, 256>>>(Wv, wv, nW);
    round_tf32_kernel<<<nW / 1024, 256>>>(Wo, wo, nW);

    // Q proj: fold 1/sqrt(D)=0.125 and tf32-round; K/V proj: tf32-round
    gemm_tf32<<<dim3(8, (Bb * Ss) / 128, 1), 256>>>(tq, wq, q, wq, q, 0.125f, 1);
    gemm_tf32<<<dim3(8, (Bb * Nn) / 128, 2), 256>>>(kvr, wk, k, wv, v, 1.0f, 1);

    vmean_part_kernel<<<dim3((Bb * Hh + 255) / 256, 16), 256>>>(v, vp);
    vmean_reduce_kernel<<<(Bb * Hh + 255) / 256, 256>>>(vp, vm);

    flash_tf32_kernel<<<dim3(Ss / 64, NHh, Bb), 128>>>(q, k, v, blk_ends, vm, ao);

    // Output projection (fp32 out, no rounding)
    gemm_tf32<<<dim3(8, (Bb * Ss) / 128, 1), 256>>>(ao, wo, out, wo, out, 1.0f, 0);
}

// round 17
// speedup vs baseline: 1.0049x; 1.0022x over previous
#include <cuda_runtime.h>
#include <math.h>
#include <float.h>
#include <stdint.h>

#define Bb 2
#define Ss 2048
#define Nn 1024
#define Hh 1024
#define NHh 16
#define Dd 64

// Scratch (__device__ globals: allocation-free rule)
__device__ float g_q[Bb * Ss * Hh];     // tf32-rounded, pre-scaled by 0.125
__device__ float g_k[Bb * Nn * Hh];     // tf32-rounded
__device__ float g_v[Bb * Nn * Hh];     // tf32-rounded
__device__ float g_ao[Bb * Ss * Hh];    // tf32-rounded attention out
__device__ float g_tq[Bb * Ss * Hh];
__device__ float g_kvr[Bb * Nn * Hh];
__device__ float g_wq[Hh * Hh];
__device__ float g_wk[Hh * Hh];
__device__ float g_wv[Hh * Hh];
__device__ float g_wo[Hh * Hh];
__device__ float g_vmean[Bb * Hh];
__device__ float g_vpart[16][Bb * Hh];

__device__ __forceinline__ float f2tf32(float x) {
    uint32_t u;
    asm("cvt.rna.tf32.f32 %0, %1;" : "=r"(u) : "f"(x));
    return __uint_as_float(u);
}

__device__ __forceinline__ void cp16(void* smem, const void* g) {
    uint32_t s = (uint32_t)__cvta_generic_to_shared(smem);
    asm volatile("cp.async.cg.shared.global [%0], [%1], 16;" :: "r"(s), "l"(g));
}

// ---------------------------------------------------------------------------
__global__ void round_tf32_kernel(const float* __restrict__ x, float* __restrict__ y, int n)
{
    int i = (blockIdx.x * blockDim.x + threadIdx.x) * 4;
    if (i >= n) return;
    float4 v = *(const float4*)(x + i);
    float4 r;
    r.x = f2tf32(v.x); r.y = f2tf32(v.y); r.z = f2tf32(v.z); r.w = f2tf32(v.w);
    *(float4*)(y + i) = r;
}

// ---------------------------------------------------------------------------
// Y[m,n] = scale * sum_k X[m,k] * W[n,k], K=N=1024. Inputs pre-rounded tf32.
// 128x128 CTA tile, K-tile 32, 256 threads, 3-stage cp.async, 1 barrier/tile.
// gridDim.z==2 selects (Wa,Ya)/(Wb,Yb). roundOut: round result to tf32.
// ---------------------------------------------------------------------------
__global__ __launch_bounds__(256) void gemm_tf32(
    const float* __restrict__ X,
    const float* __restrict__ Wa, float* __restrict__ Ya,
    const float* __restrict__ Wb, float* __restrict__ Yb,
    float scale, int roundOut)
{
    const float* W = (blockIdx.z == 0) ? Wa : Wb;
    float* Y = (blockIdx.z == 0) ? Ya : Yb;
    const int K = 1024;
    const int S = 3;
    __shared__ float As[3][128][36];
    __shared__ float Bs[3][128][36];

    int tid = threadIdx.x;
    int wid = tid >> 5;
    int lane = tid & 31;
    int m0 = blockIdx.y * 128;
    int n0 = blockIdx.x * 128;
    int warp_m = (wid >> 1) * 32;
    int warp_n = (wid & 1) * 64;
    int lr = tid >> 3;
    int lc = (tid & 7) * 4;
    const int gr = lane >> 2;
    const int gc = lane & 3;

    float acc[2][8][4];
#pragma unroll
    for (int mi = 0; mi < 2; mi++)
#pragma unroll
        for (int ni = 0; ni < 8; ni++)
#pragma unroll
            for (int r = 0; r < 4; r++) acc[mi][ni][r] = 0.f;

    // prologue: stages 0..S-2
#pragma unroll
    for (int s = 0; s < S - 1; s++) {
        int k0 = s * 32;
#pragma unroll
        for (int rr = 0; rr < 4; rr++) {
            int r = lr + rr * 32;
            cp16(&As[s][r][lc], X + (size_t)(m0 + r) * K + k0 + lc);
            cp16(&Bs[s][r][lc], W + (size_t)(n0 + r) * K + k0 + lc);
        }
        asm volatile("cp.async.commit_group;" ::: "memory");
    }

    for (int kt = 0; kt < 32; kt++) {
        int cur = kt % S;
        asm volatile("cp.async.wait_group %0;" :: "n"(S - 2) : "memory");
        __syncthreads();

        // issue load for tile kt+S-1 (writes the stage consumed at kt-1)
        if (kt + S - 1 < 32) {
            int nxt = (kt + S - 1) % S;
            int k0 = (kt + S - 1) * 32;
#pragma unroll
            for (int rr = 0; rr < 4; rr++) {
                int r = lr + rr * 32;
                cp16(&As[nxt][r][lc], X + (size_t)(m0 + r) * K + k0 + lc);
                cp16(&Bs[nxt][r][lc], W + (size_t)(n0 + r) * K + k0 + lc);
            }
            asm volatile("cp.async.commit_group;" ::: "memory");
        } else {
            asm volatile("cp.async.commit_group;" ::: "memory");   // keep group count uniform
        }

#pragma unroll
        for (int ks = 0; ks < 4; ks++) {
            int kb = ks * 8;
            uint32_t a[2][4];
#pragma unroll
            for (int mi = 0; mi < 2; mi++) {
                int r = warp_m + mi * 16 + gr;
                int c = kb + gc;
                a[mi][0] = __float_as_uint(As[cur][r][c]);
                a[mi][1] = __float_as_uint(As[cur][r + 8][c]);
                a[mi][2] = __float_as_uint(As[cur][r][c + 4]);
                a[mi][3] = __float_as_uint(As[cur][r + 8][c + 4]);
            }
            uint32_t b[8][2];
#pragma unroll
            for (int ni = 0; ni < 8; ni++) {
                int n = warp_n + ni * 8 + gr;
                int c = kb + gc;
                b[ni][0] = __float_as_uint(Bs[cur][n][c]);
                b[ni][1] = __float_as_uint(Bs[cur][n][c + 4]);
            }
#pragma unroll
            for (int mi = 0; mi < 2; mi++)
#pragma unroll
                for (int ni = 0; ni < 8; ni++) {
                    asm volatile(
                        "mma.sync.aligned.m16n8k8.row.col.f32.tf32.tf32.f32 "
                        "{%0,%1,%2,%3}, {%4,%5,%6,%7}, {%8,%9}, {%0,%1,%2,%3};\n"
                        : "+f"(acc[mi][ni][0]), "+f"(acc[mi][ni][1]),
                          "+f"(acc[mi][ni][2]), "+f"(acc[mi][ni][3])
                        : "r"(a[mi][0]), "r"(a[mi][1]), "r"(a[mi][2]), "r"(a[mi][3]),
                          "r"(b[ni][0]), "r"(b[ni][1]));
                }
        }
    }

#pragma unroll
    for (int mi = 0; mi < 2; mi++) {
#pragma unroll
        for (int ni = 0; ni < 8; ni++) {
            int row = m0 + warp_m + mi * 16 + gr;
            int col = n0 + warp_n + ni * 8 + gc * 2;
            float o0 = acc[mi][ni][0] * scale, o1 = acc[mi][ni][1] * scale;
            float o2 = acc[mi][ni][2] * scale, o3 = acc[mi][ni][3] * scale;
            if (roundOut) {
                o0 = f2tf32(o0); o1 = f2tf32(o1); o2 = f2tf32(o2); o3 = f2tf32(o3);
            }
            *(float2*)&Y[(size_t)row * 1024 + col] = make_float2(o0, o1);
            *(float2*)&Y[(size_t)(row + 8) * 1024 + col] = make_float2(o2, o3);
        }
    }
}

// ---------------------------------------------------------------------------
__global__ void vmean_part_kernel(const float* __restrict__ V, float* __restrict__ vp)
{
    int idx = blockIdx.x * blockDim.x + threadIdx.x;
    int chunk = blockIdx.y;
    if (idx >= Bb * Hh) return;
    int b = idx >> 10;
    int hd = idx & 1023;
    const float* p = V + (size_t)b * Nn * Hh + hd + (size_t)chunk * (Nn / 16) * Hh;
    float s = 0.f;
#pragma unroll 4
    for (int n = 0; n < Nn / 16; n++) s += p[(size_t)n * Hh];
    vp[chunk * (Bb * Hh) + idx] = s;
}

__global__ void vmean_reduce_kernel(const float* __restrict__ vp, float* __restrict__ vm)
{
    int idx = blockIdx.x * blockDim.x + threadIdx.x;
    if (idx >= Bb * Hh) return;
    float s = 0.f;
#pragma unroll
    for (int c = 0; c < 16; c++) s += vp[c * (Bb * Hh) + idx];
    vm[idx] = s * (1.0f / Nn);
}

// ---------------------------------------------------------------------------
// Flash attention (tf32 mma). Q pre-scaled+rounded, K/V pre-rounded.
// cp.async double-buffered KV tiles; upfront binary search over sorted
// block_ends gives the exact visible tile count (no wasted tile loads).
// 128 threads (4 warps), 64 queries/CTA, warp = 16 query rows.
// ---------------------------------------------------------------------------
__global__ __launch_bounds__(128) void flash_tf32_kernel(
    const float* __restrict__ Q, const float* __restrict__ Kp,
    const float* __restrict__ Vp, const int* __restrict__ be,
    const float* __restrict__ vmean, float* __restrict__ O)
{
    __shared__ float Qs[64][68];
    __shared__ float Ks[2][64][68];
    __shared__ float Vs[2][64][68];
    __shared__ float Ps[64][68];
    __shared__ int   bes[2][64];

    int tid = threadIdx.x;
    int wid = tid >> 5;
    int lane = tid & 31;
    const int gr = lane >> 2;
    const int gc = lane & 3;
    int b = blockIdx.z, h = blockIdx.y, t0 = blockIdx.x * 64;
    const int tmax = t0 + 63;

    const float* Qg = Q + ((size_t)b * Ss + t0) * Hh + h * Dd;
    const float* Kg = Kp + (size_t)b * Nn * Hh + h * Dd;
    const float* Vg = Vp + (size_t)b * Nn * Hh + h * Dd;

    // n_vis = #ends <= tmax (be sorted ascending); uniform binary search
    int lo = 0, hi = Nn;
    while (lo < hi) {
        int mid = (lo + hi) >> 1;
        if (be[mid] <= tmax) lo = mid + 1; else hi = mid;
    }
    const int n_tiles = (lo + 63) >> 6;

    const int rbase = wid * 16 + gr;
    float m_i[2] = {-FLT_MAX, -FLT_MAX};
    float l_i[2] = {0.f, 0.f};
    float acc[8][4];
#pragma unroll
    for (int ni = 0; ni < 8; ni++)
#pragma unroll
        for (int r = 0; r < 4; r++) acc[ni][r] = 0.f;

    // Q tile prologue load (cp.async)
#pragma unroll
    for (int p = 0; p < 8; p++) {
        int f = p * 128 + tid;
        int r = f >> 4, c = (f & 15) * 4;
        cp16(&Qs[r][c], Qg + (size_t)r * Hh + c);
    }

    if (n_tiles > 0) {
        // prefetch KV tile 0
#pragma unroll
        for (int p = 0; p < 8; p++) {
            int f = p * 128 + tid;
            int r = f >> 4, c = (f & 15) * 4;
            cp16(&Ks[0][r][c], Kg + (size_t)r * Hh + c);
            cp16(&Vs[0][r][c], Vg + (size_t)r * Hh + c);
        }
        if (tid < 64) bes[0][tid] = be[tid];
        asm volatile("cp.async.commit_group;" ::: "memory");

        for (int it = 0; it < n_tiles; it++) {
            int cur = it & 1;
            asm volatile("cp.async.wait_group 0;" ::: "memory");
            __syncthreads();

            if (it + 1 < n_tiles) {
                int nxt = cur ^ 1;
                int n0 = (it + 1) * 64;
#pragma unroll
                for (int p = 0; p < 8; p++) {
                    int f = p * 128 + tid;
                    int r = f >> 4, c = (f & 15) * 4;
                    cp16(&Ks[nxt][r][c], Kg + (size_t)(n0 + r) * Hh + c);
                    cp16(&Vs[nxt][r][c], Vg + (size_t)(n0 + r) * Hh + c);
                }
                if (tid < 64) bes[nxt][tid] = be[n0 + tid];
            }
            asm volatile("cp.async.commit_group;" ::: "memory");

            // S = Q K^T
            float s[8][4];
#pragma unroll
            for (int ni = 0; ni < 8; ni++)
#pragma unroll
                for (int r = 0; r < 4; r++) s[ni][r] = 0.f;
#pragma unroll
            for (int kb = 0; kb < 8; kb++) {
                int c = kb * 8;
                uint32_t a0 = __float_as_uint(Qs[rbase][c + gc]);
                uint32_t a1 = __float_as_uint(Qs[rbase + 8][c + gc]);
                uint32_t a2 = __float_as_uint(Qs[rbase][c + gc + 4]);
                uint32_t a3 = __float_as_uint(Qs[rbase + 8][c + gc + 4]);
#pragma unroll
                for (int ni = 0; ni < 8; ni++) {
                    uint32_t b0 = __float_as_uint(Ks[cur][ni * 8 + gr][c + gc]);
                    uint32_t b1 = __float_as_uint(Ks[cur][ni * 8 + gr][c + gc + 4]);
                    asm volatile(
                        "mma.sync.aligned.m16n8k8.row.col.f32.tf32.tf32.f32 "
                        "{%0,%1,%2,%3}, {%4,%5,%6,%7}, {%8,%9}, {%0,%1,%2,%3};\n"
                        : "+f"(s[ni][0]), "+f"(s[ni][1]), "+f"(s[ni][2]), "+f"(s[ni][3])
                        : "r"(a0), "r"(a1), "r"(a2), "r"(a3), "r"(b0), "r"(b1));
                }
            }

            int bcol[8][2];
#pragma unroll
            for (int ni = 0; ni < 8; ni++) {
                bcol[ni][0] = bes[cur][ni * 8 + gc * 2];
                bcol[ni][1] = bes[cur][ni * 8 + gc * 2 + 1];
            }

#pragma unroll
            for (int half = 0; half < 2; half++) {
                int t = t0 + rbase + half * 8;
                float sv[8][2];
                float rm = -FLT_MAX;
#pragma unroll
                for (int ni = 0; ni < 8; ni++) {
                    sv[ni][0] = (bcol[ni][0] <= t) ? s[ni][half * 2 + 0] : -FLT_MAX;
                    sv[ni][1] = (bcol[ni][1] <= t) ? s[ni][half * 2 + 1] : -FLT_MAX;
                    rm = fmaxf(rm, fmaxf(sv[ni][0], sv[ni][1]));
                }
                rm = fmaxf(rm, __shfl_xor_sync(0xffffffffu, rm, 1));
                rm = fmaxf(rm, __shfl_xor_sync(0xffffffffu, rm, 2));
                float nm = fmaxf(m_i[half], rm);
                float rl = 0.f;
                float pv[8][2];
#pragma unroll
                for (int ni = 0; ni < 8; ni++) {
                    pv[ni][0] = (sv[ni][0] == -FLT_MAX) ? 0.f : __expf(sv[ni][0] - nm);
                    pv[ni][1] = (sv[ni][1] == -FLT_MAX) ? 0.f : __expf(sv[ni][1] - nm);
                    rl += pv[ni][0] + pv[ni][1];
                }
                rl += __shfl_xor_sync(0xffffffffu, rl, 1);
                rl += __shfl_xor_sync(0xffffffffu, rl, 2);
                float alpha = (m_i[half] == nm) ? 1.f : __expf(m_i[half] - nm);
                m_i[half] = nm;
                l_i[half] = l_i[half] * alpha + rl;
                int row = rbase + half * 8;
#pragma unroll
                for (int ni = 0; ni < 8; ni++) {
                    acc[ni][half * 2 + 0] *= alpha;
                    acc[ni][half * 2 + 1] *= alpha;
                    Ps[row][ni * 8 + gc * 2]     = f2tf32(pv[ni][0]);
                    Ps[row][ni * 8 + gc * 2 + 1] = f2tf32(pv[ni][1]);
                }
            }
            __syncwarp();   // Ps rows are warp-private

            // acc += P @ V
#pragma unroll
            for (int kb = 0; kb < 8; kb++) {
                int c = kb * 8;
                uint32_t a0 = __float_as_uint(Ps[rbase][c + gc]);
                uint32_t a1 = __float_as_uint(Ps[rbase + 8][c + gc]);
                uint32_t a2 = __float_as_uint(Ps[rbase][c + gc + 4]);
                uint32_t a3 = __float_as_uint(Ps[rbase + 8][c + gc + 4]);
#pragma unroll
                for (int ni = 0; ni < 8; ni++) {
                    uint32_t b0 = __float_as_uint(Vs[cur][c + gc][ni * 8 + gr]);
                    uint32_t b1 = __float_as_uint(Vs[cur][c + gc + 4][ni * 8 + gr]);
                    asm volatile(
                        "mma.sync.aligned.m16n8k8.row.col.f32.tf32.tf32.f32 "
                        "{%0,%1,%2,%3}, {%4,%5,%6,%7}, {%8,%9}, {%0,%1,%2,%3};\n"
                        : "+f"(acc[ni][0]), "+f"(acc[ni][1]), "+f"(acc[ni][2]), "+f"(acc[ni][3])
                        : "r"(a0), "r"(a1), "r"(a2), "r"(a3), "r"(b0), "r"(b1));
                }
            }
        }
    }
    asm volatile("cp.async.wait_group 0;" ::: "memory");

    // epilogue (output rounded to tf32: feeds Wo GEMM)
    float* Og = O + ((size_t)b * Ss + t0) * Hh + h * Dd;
    const float* vmb = vmean + b * Hh + h * Dd;
#pragma unroll
    for (int half = 0; half < 2; half++) {
        int row = rbase + half * 8;
        bool uni = (l_i[half] == 0.f);
        float inv = uni ? 0.f : (1.f / l_i[half]);
#pragma unroll
        for (int ni = 0; ni < 8; ni++) {
            int col = ni * 8 + gc * 2;
            float o0 = uni ? vmb[col]     : acc[ni][half * 2 + 0] * inv;
            float o1 = uni ? vmb[col + 1] : acc[ni][half * 2 + 1] * inv;
            *(float2*)&Og[(size_t)row * Hh + col] = make_float2(f2tf32(o0), f2tf32(o1));
        }
    }
}

// ---------------------------------------------------------------------------
extern "C" void kernel_launch(void* const* d_in, const int* in_sizes, int n_in,
                              void* d_out, int out_size)
{
    const float* token_q  = (const float*)d_in[0];
    const float* block_kv = (const float*)d_in[1];
    const int*   blk_ends = (const int*)d_in[2];
    const float* Wq       = (const float*)d_in[3];
    const float* Wk       = (const float*)d_in[4];
    const float* Wv       = (const float*)d_in[5];
    const float* Wo       = (const float*)d_in[6];
    float* out = (float*)d_out;

    float *q, *k, *v, *ao, *vm, *vp, *tq, *kvr, *wq, *wk, *wv, *wo;
    cudaGetSymbolAddress((void**)&q,   g_q);
    cudaGetSymbolAddress((void**)&k,   g_k);
    cudaGetSymbolAddress((void**)&v,   g_v);
    cudaGetSymbolAddress((void**)&ao,  g_ao);
    cudaGetSymbolAddress((void**)&vm,  g_vmean);
    cudaGetSymbolAddress((void**)&vp,  g_vpart);
    cudaGetSymbolAddress((void**)&tq,  g_tq);
    cudaGetSymbolAddress((void**)&kvr, g_kvr);
    cudaGetSymbolAddress((void**)&wq,  g_wq);
    cudaGetSymbolAddress((void**)&wk,  g_wk);
    cudaGetSymbolAddress((void**)&wv,  g_wv);
    cudaGetSymbolAddress((void**)&wo,  g_wo);

    const int nTQ = Bb * Ss * Hh, nKV = Bb * Nn * Hh, nW = Hh * Hh;
    round_tf32_kernel<<<nTQ / 1024, 256>>>(token_q, tq, nTQ);
    round_tf32_kernel<<<nKV / 1024, 256>>>(block_kv, kvr, nKV);
    round_tf32_kernel<<<nW / 1024, 256>>>(Wq, wq, nW);
    round_tf32_kernel<<<nW / 1024, 256>>>(Wk, wk, nW);
    round_tf32_kernel<<<nW / 1024, 256>>>(Wv, wv, nW);
    round_tf32_kernel<<<nW / 1024, 256>>>(Wo, wo, nW);

    // Q proj: fold 1/sqrt(D)=0.125 and tf32-round; K/V proj: tf32-round
    gemm_tf32<<<dim3(8, (Bb * Ss) / 128, 1), 256>>>(tq, wq, q, wq, q, 0.125f, 1);
    gemm_tf32<<<dim3(8, (Bb * Nn) / 128, 2), 256>>>(kvr, wk, k, wv, v, 1.0f, 1);

    vmean_part_kernel<<<dim3((Bb * Hh + 255) / 256, 16), 256>>>(v, vp);
    vmean_reduce_kernel<<<(Bb * Hh + 255) / 256, 256>>>(vp, vm);

    flash_tf32_kernel<<<dim3(Ss / 64, NHh, Bb), 128>>>(q, k, v, blk_ends, vm, ao);

    // Output projection (fp32 out, no rounding)
    gemm_tf32<<<dim3(8, (Bb * Ss) / 128, 1), 256>>>(ao, wo, out, wo, out, 1.0f, 0);
}